// round 14
// baseline (speedup 1.0000x reference)
#include <cuda_runtime.h>
#include <cuda_fp16.h>
#include <math.h>
#include <stdint.h>

// ---------------- problem dims ----------------
#define Bdim 8
#define Sdim 1024
#define Ddim 768
#define Hn   12
#define DHn  64
#define MLPn 3072
#define Rn   (Bdim*Sdim)          // 8192 rows
#define HALF_S 512

// ---------------- scratch (device globals) ----------------
__device__ float g_x1[Rn*Ddim];
__device__ float g_ctxbar[Bdim*Ddim];
__device__ float g_abar[Bdim*Ddim];
__device__ __half g_xn [Rn*Ddim];
__device__ __half g_qh [Rn*Ddim];
__device__ __half g_kh [Rn*Ddim];
__device__ __half g_vh [Rn*Ddim];
__device__ __half g_ct [Rn*Ddim];
__device__ __half g_x2 [Rn*Ddim];
__device__ __half g_h1 [Rn*MLPn];
// fp16 transposed weights [N, K] K-major; qkv concatenated [2304, 768]
__device__ __half g_wqkv[3*Ddim*Ddim];
__device__ __half g_wo[Ddim*Ddim];
__device__ __half g_w1[MLPn*Ddim];
__device__ __half g_w2[Ddim*MLPn];

// ---------------- helpers ----------------
__device__ __forceinline__ uint32_t smem_u32(const void* p){
    uint32_t a;
    asm("{ .reg .u64 t; cvta.to.shared.u64 t, %1; cvt.u32.u64 %0, t; }" : "=r"(a) : "l"(p));
    return a;
}
__device__ __forceinline__ uint32_t pack2h(float a, float b){
    __half2 h = __floats2half2_rn(a, b);
    return *(uint32_t*)&h;
}

#define CP_ASYNC16(sdst, gsrc) \
    asm volatile("cp.async.cg.shared.global [%0], [%1], 16;" :: "r"(sdst), "l"(gsrc) : "memory")
#define CP_COMMIT()  asm volatile("cp.async.commit_group;" ::: "memory")
#define CP_WAIT1()   asm volatile("cp.async.wait_group 1;" ::: "memory")
#define CP_WAIT0()   asm volatile("cp.async.wait_group 0;" ::: "memory")

#define LDSM4(R, A) \
    asm volatile("ldmatrix.sync.aligned.m8n8.x4.shared.b16 {%0,%1,%2,%3}, [%4];" \
        : "=r"((R)[0]), "=r"((R)[1]), "=r"((R)[2]), "=r"((R)[3]) : "r"(A))
#define LDSM4T(R, A) \
    asm volatile("ldmatrix.sync.aligned.m8n8.x4.trans.shared.b16 {%0,%1,%2,%3}, [%4];" \
        : "=r"((R)[0]), "=r"((R)[1]), "=r"((R)[2]), "=r"((R)[3]) : "r"(A))

#define MMA16816(D, Aa, Bb) \
    asm volatile("mma.sync.aligned.m16n8k16.row.col.f32.f16.f16.f32 " \
        "{%0,%1,%2,%3}, {%4,%5,%6,%7}, {%8,%9}, {%0,%1,%2,%3};" \
        : "+f"((D)[0]), "+f"((D)[1]), "+f"((D)[2]), "+f"((D)[3]) \
        : "r"((Aa)[0]), "r"((Aa)[1]), "r"((Aa)[2]), "r"((Aa)[3]), \
          "r"((Bb)[0]), "r"((Bb)[1]))

// ---------------- LayerNorm core (full 768-col row in one block) ----------------
__device__ __forceinline__ void ln_row_to_fp16(
    float v0, float v1, float v2,
    const float* __restrict__ g, const float* __restrict__ b,
    __half* __restrict__ y, size_t ob, int tid)
{
    float s = v0 + v1 + v2;
    float q = v0*v0 + v1*v1 + v2*v2;
    #pragma unroll
    for (int o = 16; o; o >>= 1) {
        s += __shfl_xor_sync(0xffffffffu, s, o);
        q += __shfl_xor_sync(0xffffffffu, q, o);
    }
    __shared__ float rs[8], rq[8];
    if ((tid & 31) == 0) { rs[tid >> 5] = s; rq[tid >> 5] = q; }
    __syncthreads();
    float ts = 0.f, tq = 0.f;
    #pragma unroll
    for (int i = 0; i < 8; i++) { ts += rs[i]; tq += rq[i]; }
    float mu   = ts * (1.0f / Ddim);
    float var  = tq * (1.0f / Ddim) - mu * mu;
    float rstd = rsqrtf(var + 1e-6f);

    y[ob + tid]       = __float2half((v0 - mu) * rstd * g[tid]       + b[tid]);
    y[ob + tid + 256] = __float2half((v1 - mu) * rstd * g[tid + 256] + b[tid + 256]);
    y[ob + tid + 512] = __float2half((v2 - mu) * rstd * g[tid + 512] + b[tid + 512]);
}

// ---------------- prep: weight transpose (blocks 0..6911) + LN1 (rest) ----------------
struct WEnt { const float* src; __half* dh; int K, N, tile0; };
struct WTab { WEnt e[6]; };
#define WTILES 6912

__global__ __launch_bounds__(256) void prep_kernel(
    WTab tab, const float* __restrict__ x,
    const float* __restrict__ ln1g, const float* __restrict__ ln1b,
    __half* __restrict__ xn)
{
    int bt = blockIdx.x;
    int tid = threadIdx.x;
    if (bt < WTILES) {
        __shared__ float t[32][33];
        int ei = 0;
        #pragma unroll
        for (int i = 1; i < 6; i++) if (bt >= tab.e[i].tile0) ei = i;
        const WEnt w = tab.e[ei];
        int lt = bt - w.tile0;
        int nt = w.N / 32;
        int n0 = (lt % nt) * 32, k0 = (lt / nt) * 32;
        int tx = tid & 31, ty = tid >> 5;
        #pragma unroll
        for (int i = ty; i < 32; i += 8)
            t[i][tx] = w.src[(size_t)(k0 + i) * w.N + n0 + tx];
        __syncthreads();
        #pragma unroll
        for (int i = ty; i < 32; i += 8)
            w.dh[(size_t)(n0 + i) * w.K + k0 + tx] = __float2half(t[tx][i]);
    } else {
        int row = bt - WTILES;
        size_t ob = (size_t)row * Ddim;
        float v0 = x[ob + tid], v1 = x[ob + tid + 256], v2 = x[ob + tid + 512];
        ln_row_to_fp16(v0, v1, v2, ln1g, ln1b, xn, ob, tid);
    }
}

// ---------------- ln2_all: x2 = LN2(x1) all rows; upper rows build x1 = x + abar ----------------
__global__ __launch_bounds__(256) void ln2_all_kernel(
    const float* __restrict__ x, const float* __restrict__ abar,
    const float* __restrict__ g, const float* __restrict__ b,
    float* __restrict__ x1, __half* __restrict__ x2)
{
    int row = blockIdx.x;
    int r = row & (Sdim - 1);
    size_t ob = (size_t)row * Ddim;
    int tid = threadIdx.x;
    float v0, v1, v2;
    if (r >= HALF_S) {
        const float* ab = abar + (row >> 10) * Ddim;
        v0 = x[ob + tid]       + ab[tid];
        v1 = x[ob + tid + 256] + ab[tid + 256];
        v2 = x[ob + tid + 512] + ab[tid + 512];
        x1[ob + tid]       = v0;
        x1[ob + tid + 256] = v1;
        x1[ob + tid + 512] = v2;
    } else {
        v0 = x1[ob + tid];
        v1 = x1[ob + tid + 256];
        v2 = x1[ob + tid + 512];
    }
    ln_row_to_fp16(v0, v1, v2, g, b, x2, ob, tid);
}

// ---------------- fp16 1-pass HMMA GEMM: C = A @ B ----------------
// 128x128 CTA tile, 4 warps (warp tile 64x64), BK=64, 3-stage, 2 CTAs/SM.
// MODE 0: fp32 out (+bias, optional res). MODE 1: fp16 out (+bias, +RELU).
// MODE 2: QKV trio fp16 out; seg 0 (q) computes only lower-512 row tiles.
// HALFM: A/res/out rows are the lower 512 of each batch.
// ABAR: blocks with bn >= N/128 each compute one 32-col abar unit (192 blocks).
#define GLDS  144u
#define GTBA  18432u     // 128 * 144
#define GSTG  36864u     // 2 tiles
#define GSM   110592     // 3 stages

template<int MODE, bool RELU, bool RES, bool HALFM, bool ABAR>
__global__ __launch_bounds__(128, 2) void gemm_mma(
    const __half* __restrict__ A, const __half* __restrict__ B,
    const float* __restrict__ bias0, const float* __restrict__ bias1,
    const float* __restrict__ bias2, const float* __restrict__ res,
    float* __restrict__ outF,
    __half* __restrict__ o0, __half* __restrict__ o1, __half* __restrict__ o2,
    const float* __restrict__ ctxbar, const float* __restrict__ Wo32,
    float* __restrict__ abar,
    int N, int K)
{
    extern __shared__ char smem[];
    uint32_t sbase = smem_u32(smem);
    int tid = threadIdx.x;
    int lane = tid & 31, wid = tid >> 5;
    int wm = wid >> 1, wn = wid & 1;
    int bn = blockIdx.x, bm = blockIdx.y;

    if (ABAR && bn >= N / 128) {
        // ---- abar unit: u in [0,192): b = u/24, n0 = (u%24)*32 ----
        float* red = (float*)smem;   // 4 x 33 floats
        int u = (bn - N / 128) * 32 + bm;
        int b = u / 24;
        int n = (u % 24) * 32 + (tid & 31);
        int ty = tid >> 5;           // 4 k-slices
        const float* cb = ctxbar + b * Ddim;
        float s = 0.f;
        #pragma unroll 8
        for (int k = ty; k < Ddim; k += 4)
            s += cb[k] * Wo32[(size_t)k * Ddim + n];
        red[ty * 33 + (tid & 31)] = s;
        __syncthreads();
        if (ty == 0) {
            float t = bias0[n];
            #pragma unroll
            for (int i = 0; i < 4; i++) t += red[i * 33 + (tid & 31)];
            abar[b * Ddim + n] = t;
        }
        return;
    }

    int seg = 0;
    if (MODE == 2) {
        seg = (bn * 128) / Ddim;
        if (seg == 0 && (bm & 7) >= 4) return;   // q tiles only for lower rows
    }

    int rowg = HALFM ? ((bm >> 2) * Sdim + (bm & 3) * 128) : bm * 128;

    const __half* pA = A + (size_t)rowg * K;
    const __half* pB = B + (size_t)(bn * 128) * K;

    int CH = K >> 6;

    auto load_chunk = [&](int c, int stg){
        int c0 = c * 64;
        uint32_t sb = sbase + (uint32_t)stg * GSTG;
        #pragma unroll
        for (int i = 0; i < 16; i++) {
            int g = i * 128 + tid;
            int tI = g >> 10;
            int w  = g & 1023;
            int rr = w >> 3;
            int cc = w & 7;
            const __half* base = tI ? pB : pA;
            const __half* gp = base + (size_t)rr * K + c0 + cc * 8;
            uint32_t s = sb + (uint32_t)tI * GTBA + (uint32_t)rr * GLDS + (uint32_t)cc * 16;
            CP_ASYNC16(s, gp);
        }
        CP_COMMIT();
    };

    load_chunk(0, 0);
    load_chunk(1, 1);

    float acc[4][8][4];
    #pragma unroll
    for (int i = 0; i < 4; i++)
        #pragma unroll
        for (int j = 0; j < 8; j++)
            #pragma unroll
            for (int e = 0; e < 4; e++) acc[i][j][e] = 0.f;

    uint32_t a_lane = (uint32_t)((lane & 15) * GLDS + (lane >> 4) * 16);
    uint32_t b_lane = (uint32_t)((lane & 7) * GLDS + ((lane >> 3) & 1) * 16 + (lane >> 4) * (8 * GLDS));

    for (int c = 0; c < CH; c++) {
        if (c + 1 < CH) { CP_WAIT1(); } else { CP_WAIT0(); }
        __syncthreads();
        if (c + 2 < CH) load_chunk(c + 2, (c + 2) % 3);

        uint32_t stg = sbase + (uint32_t)(c % 3) * GSTG;
        uint32_t aS = stg, bS = stg + GTBA;

        #pragma unroll
        for (int ks = 0; ks < 4; ks++) {
            uint32_t ko = (uint32_t)ks * 32;
            uint32_t ah[4][4], bh[4][4];
            #pragma unroll
            for (int i = 0; i < 4; i++) {
                uint32_t off = (uint32_t)((wm * 64 + i * 16) * GLDS) + a_lane + ko;
                LDSM4(ah[i], aS + off);
            }
            #pragma unroll
            for (int jp = 0; jp < 4; jp++) {
                uint32_t off = (uint32_t)((wn * 64 + jp * 16) * GLDS) + b_lane + ko;
                LDSM4(bh[jp], bS + off);
            }
            #pragma unroll
            for (int i = 0; i < 4; i++)
                #pragma unroll
                for (int j = 0; j < 8; j++)
                    MMA16816(acc[i][j], ah[i], &bh[j >> 1][(j & 1) * 2]);
        }
    }

    // epilogue
    const float* bsel = bias0;
    __half* Hsel = o0;
    if (MODE == 2) {
        bsel = (seg == 0) ? bias0 : (seg == 1) ? bias1 : bias2;
        Hsel = (seg == 0) ? o0 : (seg == 1) ? o1 : o2;
    }
    int ostride = (MODE == 2) ? Ddim : N;
    int r_base = rowg + wm * 64 + (lane >> 2);
    int c_base = bn * 128 + wn * 64 + (lane & 3) * 2 - ((MODE == 2) ? seg * Ddim : 0);

    #pragma unroll
    for (int i = 0; i < 4; i++) {
        #pragma unroll
        for (int j = 0; j < 8; j++) {
            int row0 = r_base + i * 16;
            int col  = c_base + j * 8;
            float2 bv = *(const float2*)(bsel + col);
            float v00 = acc[i][j][0] + bv.x, v01 = acc[i][j][1] + bv.y;
            float v10 = acc[i][j][2] + bv.x, v11 = acc[i][j][3] + bv.y;
            size_t ox0 = (size_t)row0 * ostride + col;
            size_t ox1 = ox0 + (size_t)8 * ostride;
            if (MODE == 0 && RES) {
                float2 r0 = *(const float2*)(res + ox0);
                float2 r1 = *(const float2*)(res + ox1);
                v00 += r0.x; v01 += r0.y; v10 += r1.x; v11 += r1.y;
            }
            if (RELU) {
                v00 = fmaxf(v00, 0.f); v01 = fmaxf(v01, 0.f);
                v10 = fmaxf(v10, 0.f); v11 = fmaxf(v11, 0.f);
            }
            if (MODE == 0) {
                *(float2*)(outF + ox0) = make_float2(v00, v01);
                *(float2*)(outF + ox1) = make_float2(v10, v11);
            } else {
                *(uint32_t*)(Hsel + ox0) = pack2h(v00, v01);
                *(uint32_t*)(Hsel + ox1) = pack2h(v10, v11);
            }
        }
    }
}

// ---------------- HMMA flash attention + fused ctxmean blocks ----------------
// grid (96, 10): qt < 8 -> attention tile; qt >= 8 -> ctxmean block.
#define AST 144u
#define PST 272u
#define A_SQH 0u
#define A_SK  9216u       // 2 stages x 18432
#define A_SV  46080u      // 2 stages x 18432
#define A_SP  82944u
#define A_PSUM 100352u
#define ATTN_SMEM 100864

__global__ __launch_bounds__(256) void attn_mma_kernel(
    const __half* __restrict__ Qh, const __half* __restrict__ Kh,
    const __half* __restrict__ Vh, __half* __restrict__ OH,
    float* __restrict__ ctxbar)
{
    extern __shared__ char smraw[];
    uint32_t S = smem_u32(smraw);
    int bh = blockIdx.x, qt = blockIdx.y;
    int tid = threadIdx.x, lane = tid & 31, wid = tid >> 5;

    if (qt >= 8) {
        __shared__ float red[8][33];
        int idx = bh * 2 + (qt - 8);
        int b = idx / 24;
        int n0 = (idx % 24) * 32;
        int tx = tid & 31, ty = tid >> 5;
        size_t base = ((size_t)b * Sdim + ty) * Ddim + n0 + tx;
        float s = 0.f;
        #pragma unroll 4
        for (int r = ty; r < Sdim; r += 8)
            s += __half2float(Vh[base + (size_t)(r - ty) * Ddim]);
        red[ty][tx] = s;
        __syncthreads();
        if (ty == 0) {
            float t = 0.f;
            #pragma unroll
            for (int i = 0; i < 8; i++) t += red[i][tx];
            ctxbar[b * Ddim + n0 + tx] = t * (1.0f / Sdim);
        }
        return;
    }

    float* psum = (float*)(smraw + A_PSUM);
    int b = bh / Hn, h = bh % Hn;
    int wm = wid >> 1, wn = wid & 1;

    const size_t cb = (size_t)h * DHn;
    const __half* Qg = Qh + ((size_t)(b * Sdim + qt * 64)) * Ddim + cb;
    const __half* Kg = Kh + ((size_t)(b * Sdim)) * Ddim + cb;
    const __half* Vg = Vh + ((size_t)(b * Sdim)) * Ddim + cb;

    auto load_kv = [&](int t, int s){
        uint32_t kb = S + A_SK + (uint32_t)s * 18432u;
        uint32_t vb = S + A_SV + (uint32_t)s * 18432u;
        #pragma unroll
        for (int i = 0; i < 8; i++) {
            int idx = ((i & 3) << 8) + tid;
            int r = idx >> 3, c = idx & 7;
            const __half* src = (i < 4 ? Kg : Vg) + (size_t)(t * 128 + r) * Ddim + c * 8;
            uint32_t dst = (i < 4 ? kb : vb) + (uint32_t)r * AST + (uint32_t)c * 16;
            CP_ASYNC16(dst, src);
        }
        CP_COMMIT();
    };

    #pragma unroll
    for (int i = 0; i < 2; i++) {
        int idx = (i << 8) + tid;
        int r = idx >> 3, c = idx & 7;
        const __half* src = Qg + (size_t)r * Ddim + c * 8;
        CP_ASYNC16(S + A_SQH + (uint32_t)r * AST + (uint32_t)c * 16, src);
    }
    {
        uint32_t kb = S + A_SK, vb = S + A_SV;
        #pragma unroll
        for (int i = 0; i < 8; i++) {
            int idx = ((i & 3) << 8) + tid;
            int r = idx >> 3, c = idx & 7;
            const __half* src = (i < 4 ? Kg : Vg) + (size_t)r * Ddim + c * 8;
            uint32_t dst = (i < 4 ? kb : vb) + (uint32_t)r * AST + (uint32_t)c * 16;
            CP_ASYNC16(dst, src);
        }
        CP_COMMIT();
    }
    load_kv(1, 1);

    float oacc[4][4];
    #pragma unroll
    for (int j = 0; j < 4; j++)
        #pragma unroll
        for (int e = 0; e < 4; e++) oacc[j][e] = 0.f;
    float l0 = 0.f, l1 = 0.f;

    uint32_t qF[4][4];
    int r0 = wm * 16 + (lane >> 2);

    const int NKT = Sdim / 128;
    for (int t = 0; t < NKT; t++) {
        int s = t & 1;
        if (t + 1 < NKT) { CP_WAIT1(); } else { CP_WAIT0(); }
        __syncthreads();

        if (t == 0) {
            #pragma unroll
            for (int ks = 0; ks < 4; ks++) {
                uint32_t off = (uint32_t)((wm * 16 + (lane & 15)) * AST)
                             + (uint32_t)((lane >> 4) * 16) + (uint32_t)ks * 32;
                LDSM4(qF[ks], S + A_SQH + off);
            }
        }

        uint32_t kb = S + A_SK + (uint32_t)s * 18432u;
        uint32_t vb = S + A_SV + (uint32_t)s * 18432u;

        float sacc[8][4];
        #pragma unroll
        for (int j = 0; j < 8; j++)
            #pragma unroll
            for (int e = 0; e < 4; e++) sacc[j][e] = 0.f;

        uint32_t bl_lane = (uint32_t)((lane & 7) * AST + ((lane >> 3) & 1) * 16
                                      + (lane >> 4) * (8 * AST));
        #pragma unroll
        for (int ks = 0; ks < 4; ks++) {
            uint32_t kf[4][4];
            #pragma unroll
            for (int np = 0; np < 4; np++) {
                uint32_t off = (uint32_t)((wn * 64 + np * 16) * AST) + bl_lane + (uint32_t)ks * 32;
                LDSM4(kf[np], kb + off);
            }
            #pragma unroll
            for (int j = 0; j < 8; j++)
                MMA16816(sacc[j], qF[ks], &kf[j >> 1][(j & 1) * 2]);
        }

        float s0 = 0.f, s1 = 0.f;
        uint32_t prow0 = S + A_SP + (uint32_t)(r0 * PST);
        uint32_t prow1 = S + A_SP + (uint32_t)((r0 + 8) * PST);
        uint32_t coff = (uint32_t)((wn * 64 + (lane & 3) * 2) * 2);
        #pragma unroll
        for (int j = 0; j < 8; j++) {
            float p00 = __expf(sacc[j][0] * 0.125f);
            float p01 = __expf(sacc[j][1] * 0.125f);
            float p10 = __expf(sacc[j][2] * 0.125f);
            float p11 = __expf(sacc[j][3] * 0.125f);
            s0 += p00 + p01; s1 += p10 + p11;
            uint32_t u0 = pack2h(p00, p01), u1 = pack2h(p10, p11);
            asm volatile("st.shared.b32 [%0], %1;" :: "r"(prow0 + coff + j * 16), "r"(u0) : "memory");
            asm volatile("st.shared.b32 [%0], %1;" :: "r"(prow1 + coff + j * 16), "r"(u1) : "memory");
        }
        l0 += s0; l1 += s1;
        __syncthreads();

        #pragma unroll
        for (int ks = 0; ks < 8; ks++) {
            uint32_t pf[4];
            uint32_t aoff = (uint32_t)((wm * 16 + (lane & 15)) * PST)
                          + (uint32_t)((lane >> 4) * 16) + (uint32_t)ks * 32;
            LDSM4(pf, S + A_SP + aoff);
            #pragma unroll
            for (int np = 0; np < 2; np++) {
                uint32_t vf[4];
                uint32_t voff = (uint32_t)((ks * 16 + (lane & 15)) * AST)
                              + (uint32_t)(wn * 64 + np * 32) + (uint32_t)((lane >> 4) * 16);
                LDSM4T(vf, vb + voff);
                MMA16816(oacc[np * 2 + 0], pf, &vf[0]);
                MMA16816(oacc[np * 2 + 1], pf, &vf[2]);
            }
        }

        __syncthreads();
        if (t + 2 < NKT) load_kv(t + 2, s);
    }

    l0 += __shfl_xor_sync(0xffffffffu, l0, 1);
    l0 += __shfl_xor_sync(0xffffffffu, l0, 2);
    l1 += __shfl_xor_sync(0xffffffffu, l1, 1);
    l1 += __shfl_xor_sync(0xffffffffu, l1, 2);
    if ((lane & 3) == 0) {
        psum[r0 * 2 + wn] = l0;
        psum[(r0 + 8) * 2 + wn] = l1;
    }
    __syncthreads();
    float inv0 = 1.0f / (psum[r0 * 2] + psum[r0 * 2 + 1]);
    float inv1 = 1.0f / (psum[(r0 + 8) * 2] + psum[(r0 + 8) * 2 + 1]);

    size_t grow0 = ((size_t)(b * Sdim + qt * 64 + r0)) * Ddim + cb + wn * 32 + (lane & 3) * 2;
    size_t grow1 = grow0 + (size_t)8 * Ddim;
    #pragma unroll
    for (int j = 0; j < 4; j++) {
        *(uint32_t*)(OH + grow0 + j * 8) = pack2h(oacc[j][0] * inv0, oacc[j][1] * inv0);
        *(uint32_t*)(OH + grow1 + j * 8) = pack2h(oacc[j][2] * inv1, oacc[j][3] * inv1);
    }
}

// ---------------- launcher ----------------
extern "C" void kernel_launch(void* const* d_in, const int* in_sizes, int n_in,
                              void* d_out, int out_size)
{
    const float* x    = (const float*)d_in[0];
    const float* Wq   = (const float*)d_in[1];
    const float* bq   = (const float*)d_in[2];
    const float* Wk   = (const float*)d_in[3];
    const float* bk   = (const float*)d_in[4];
    const float* Wv   = (const float*)d_in[5];
    const float* bv   = (const float*)d_in[6];
    const float* Wo   = (const float*)d_in[7];
    const float* bo   = (const float*)d_in[8];
    const float* ln1g = (const float*)d_in[9];
    const float* ln1b = (const float*)d_in[10];
    const float* ln2g = (const float*)d_in[11];
    const float* ln2b = (const float*)d_in[12];
    const float* W1   = (const float*)d_in[13];
    const float* b1   = (const float*)d_in[14];
    const float* W2   = (const float*)d_in[15];
    const float* b2   = (const float*)d_in[16];
    float* out = (float*)d_out;

    float *x1, *ctxbar, *abar;
    __half *xn, *qh, *kh, *vh, *ct, *x2, *h1;
    __half *wqkv, *wo, *w1, *w2;
    cudaGetSymbolAddress((void**)&x1,  g_x1);
    cudaGetSymbolAddress((void**)&ctxbar, g_ctxbar);
    cudaGetSymbolAddress((void**)&abar,   g_abar);
    cudaGetSymbolAddress((void**)&xn,  g_xn);
    cudaGetSymbolAddress((void**)&qh,  g_qh);
    cudaGetSymbolAddress((void**)&kh,  g_kh);
    cudaGetSymbolAddress((void**)&vh,  g_vh);
    cudaGetSymbolAddress((void**)&ct,  g_ct);
    cudaGetSymbolAddress((void**)&x2,  g_x2);
    cudaGetSymbolAddress((void**)&h1,  g_h1);
    cudaGetSymbolAddress((void**)&wqkv, g_wqkv);
    cudaGetSymbolAddress((void**)&wo,  g_wo);
    cudaGetSymbolAddress((void**)&w1,  g_w1);
    cudaGetSymbolAddress((void**)&w2,  g_w2);

    cudaFuncSetAttribute(attn_mma_kernel, cudaFuncAttributeMaxDynamicSharedMemorySize, ATTN_SMEM);
    cudaFuncSetAttribute(gemm_mma<2,false,false,false,false>, cudaFuncAttributeMaxDynamicSharedMemorySize, GSM);
    cudaFuncSetAttribute(gemm_mma<0,false,true ,true ,true >, cudaFuncAttributeMaxDynamicSharedMemorySize, GSM);
    cudaFuncSetAttribute(gemm_mma<1,true ,false,false,false>, cudaFuncAttributeMaxDynamicSharedMemorySize, GSM);
    cudaFuncSetAttribute(gemm_mma<0,false,true ,false,false>, cudaFuncAttributeMaxDynamicSharedMemorySize, GSM);

    WTab tab;
    tab.e[0] = { Wq, wqkv,               Ddim, Ddim, 0    };
    tab.e[1] = { Wk, wqkv + Ddim*Ddim,   Ddim, Ddim, 576  };
    tab.e[2] = { Wv, wqkv + 2*Ddim*Ddim, Ddim, Ddim, 1152 };
    tab.e[3] = { Wo, wo,                 Ddim, Ddim, 1728 };
    tab.e[4] = { W1, w1,                 Ddim, MLPn, 2304 };
    tab.e[5] = { W2, w2,                 MLPn, Ddim, 4608 };

    // 1. weight transpose + LN1
    prep_kernel<<<WTILES + Rn, 256>>>(tab, x, ln1g, ln1b, xn);

    // 2. fused QKV (q: lower rows only; k,v: all rows)
    gemm_mma<2,false,false,false,false><<<dim3(3*Ddim/128, Rn/128), 128, GSM>>>(
        xn, wqkv, bq, bk, bv, nullptr, nullptr,
        qh, kh, vh, nullptr, nullptr, nullptr, 3*Ddim, Ddim);

    // 3. attention (rows < 512) + fused ctxmean blocks
    attn_mma_kernel<<<dim3(Bdim*Hn, 10), 256, ATTN_SMEM>>>(qh, kh, vh, ct, ctxbar);

    // 4. Wo + residual, lower rows; bn in 6..11 -> 192 one-unit abar blocks (hidden)
    gemm_mma<0,false,true,true,true><<<dim3(Ddim/128 + 6, (Rn/2)/128), 128, GSM>>>(
        ct, wo, bo, nullptr, nullptr, x, x1,
        nullptr, nullptr, nullptr, ctxbar, Wo, abar, Ddim, Ddim);

    // 5. x2 = LN2 all rows; upper rows also build x1 = x + abar
    ln2_all_kernel<<<Rn, 256>>>(x, abar, ln2g, ln2b, x1, x2);

    // 6. MLP1 (ReLU, fp16 out)  (ncu profiles this launch)
    gemm_mma<1,true,false,false,false><<<dim3(MLPn/128, Rn/128), 128, GSM>>>(
        x2, w1, b1, nullptr, nullptr, nullptr, nullptr,
        h1, nullptr, nullptr, nullptr, nullptr, nullptr, MLPn, Ddim);

    // 7. MLP2 + residual -> out
    gemm_mma<0,false,true,false,false><<<dim3(Ddim/128, Rn/128), 128, GSM>>>(
        h1, w2, b2, nullptr, nullptr, x1, out,
        nullptr, nullptr, nullptr, nullptr, nullptr, nullptr, Ddim, MLPn);
}

// round 15
// speedup vs baseline: 1.0465x; 1.0465x over previous
#include <cuda_runtime.h>
#include <cuda_fp16.h>
#include <math.h>
#include <stdint.h>

// ---------------- problem dims ----------------
#define Bdim 8
#define Sdim 1024
#define Ddim 768
#define Hn   12
#define DHn  64
#define MLPn 3072
#define Rn   (Bdim*Sdim)          // 8192 rows
#define HALF_S 512

// ---------------- scratch (device globals) ----------------
__device__ float g_x1[Rn*Ddim];
__device__ float g_ctxbar[Bdim*Ddim];
__device__ float g_abar[Bdim*Ddim];
__device__ __half g_xn [Rn*Ddim];
__device__ __half g_qh [Rn*Ddim];
__device__ __half g_kh [Rn*Ddim];
__device__ __half g_vh [Rn*Ddim];
__device__ __half g_ct [Rn*Ddim];
__device__ __half g_x2 [Rn*Ddim];
__device__ __half g_h1 [Rn*MLPn];
// fp16 transposed weights [N, K] K-major; qkv concatenated [2304, 768]
__device__ __half g_wqkv[3*Ddim*Ddim];
__device__ __half g_wo[Ddim*Ddim];
__device__ __half g_w1[MLPn*Ddim];
__device__ __half g_w2[Ddim*MLPn];

// ---------------- helpers ----------------
__device__ __forceinline__ uint32_t smem_u32(const void* p){
    uint32_t a;
    asm("{ .reg .u64 t; cvta.to.shared.u64 t, %1; cvt.u32.u64 %0, t; }" : "=r"(a) : "l"(p));
    return a;
}
__device__ __forceinline__ uint32_t pack2h(float a, float b){
    __half2 h = __floats2half2_rn(a, b);
    return *(uint32_t*)&h;
}

#define CP_ASYNC16(sdst, gsrc) \
    asm volatile("cp.async.cg.shared.global [%0], [%1], 16;" :: "r"(sdst), "l"(gsrc) : "memory")
#define CP_COMMIT()  asm volatile("cp.async.commit_group;" ::: "memory")
#define CP_WAIT1()   asm volatile("cp.async.wait_group 1;" ::: "memory")
#define CP_WAIT0()   asm volatile("cp.async.wait_group 0;" ::: "memory")

#define LDSM4(R, A) \
    asm volatile("ldmatrix.sync.aligned.m8n8.x4.shared.b16 {%0,%1,%2,%3}, [%4];" \
        : "=r"((R)[0]), "=r"((R)[1]), "=r"((R)[2]), "=r"((R)[3]) : "r"(A))
#define LDSM4T(R, A) \
    asm volatile("ldmatrix.sync.aligned.m8n8.x4.trans.shared.b16 {%0,%1,%2,%3}, [%4];" \
        : "=r"((R)[0]), "=r"((R)[1]), "=r"((R)[2]), "=r"((R)[3]) : "r"(A))

#define MMA16816(D, Aa, Bb) \
    asm volatile("mma.sync.aligned.m16n8k16.row.col.f32.f16.f16.f32 " \
        "{%0,%1,%2,%3}, {%4,%5,%6,%7}, {%8,%9}, {%0,%1,%2,%3};" \
        : "+f"((D)[0]), "+f"((D)[1]), "+f"((D)[2]), "+f"((D)[3]) \
        : "r"((Aa)[0]), "r"((Aa)[1]), "r"((Aa)[2]), "r"((Aa)[3]), \
          "r"((Bb)[0]), "r"((Bb)[1]))

// ---------------- LayerNorm core (full 768-col row in one block) ----------------
__device__ __forceinline__ void ln_row_to_fp16(
    float v0, float v1, float v2,
    const float* __restrict__ g, const float* __restrict__ b,
    __half* __restrict__ y, size_t ob, int tid)
{
    float s = v0 + v1 + v2;
    float q = v0*v0 + v1*v1 + v2*v2;
    #pragma unroll
    for (int o = 16; o; o >>= 1) {
        s += __shfl_xor_sync(0xffffffffu, s, o);
        q += __shfl_xor_sync(0xffffffffu, q, o);
    }
    __shared__ float rs[8], rq[8];
    if ((tid & 31) == 0) { rs[tid >> 5] = s; rq[tid >> 5] = q; }
    __syncthreads();
    float ts = 0.f, tq = 0.f;
    #pragma unroll
    for (int i = 0; i < 8; i++) { ts += rs[i]; tq += rq[i]; }
    float mu   = ts * (1.0f / Ddim);
    float var  = tq * (1.0f / Ddim) - mu * mu;
    float rstd = rsqrtf(var + 1e-6f);

    y[ob + tid]       = __float2half((v0 - mu) * rstd * g[tid]       + b[tid]);
    y[ob + tid + 256] = __float2half((v1 - mu) * rstd * g[tid + 256] + b[tid + 256]);
    y[ob + tid + 512] = __float2half((v2 - mu) * rstd * g[tid + 512] + b[tid + 512]);
}

// ---------------- prep: weight transpose (blocks 0..6911) + LN1 (rest) ----------------
struct WEnt { const float* src; __half* dh; int K, N, tile0; };
struct WTab { WEnt e[6]; };
#define WTILES 6912

__global__ __launch_bounds__(256) void prep_kernel(
    WTab tab, const float* __restrict__ x,
    const float* __restrict__ ln1g, const float* __restrict__ ln1b,
    __half* __restrict__ xn)
{
    int bt = blockIdx.x;
    int tid = threadIdx.x;
    if (bt < WTILES) {
        __shared__ float t[32][33];
        int ei = 0;
        #pragma unroll
        for (int i = 1; i < 6; i++) if (bt >= tab.e[i].tile0) ei = i;
        const WEnt w = tab.e[ei];
        int lt = bt - w.tile0;
        int nt = w.N / 32;
        int n0 = (lt % nt) * 32, k0 = (lt / nt) * 32;
        int tx = tid & 31, ty = tid >> 5;
        #pragma unroll
        for (int i = ty; i < 32; i += 8)
            t[i][tx] = w.src[(size_t)(k0 + i) * w.N + n0 + tx];
        __syncthreads();
        #pragma unroll
        for (int i = ty; i < 32; i += 8)
            w.dh[(size_t)(n0 + i) * w.K + k0 + tx] = __float2half(t[tx][i]);
    } else {
        int row = bt - WTILES;
        size_t ob = (size_t)row * Ddim;
        float v0 = x[ob + tid], v1 = x[ob + tid + 256], v2 = x[ob + tid + 512];
        ln_row_to_fp16(v0, v1, v2, ln1g, ln1b, xn, ob, tid);
    }
}

// ---------------- ln2_all: x2 = LN2(x1) all rows; upper rows build x1 = x + abar ----------------
__global__ __launch_bounds__(256) void ln2_all_kernel(
    const float* __restrict__ x, const float* __restrict__ abar,
    const float* __restrict__ g, const float* __restrict__ b,
    float* __restrict__ x1, __half* __restrict__ x2)
{
    int row = blockIdx.x;
    int r = row & (Sdim - 1);
    size_t ob = (size_t)row * Ddim;
    int tid = threadIdx.x;
    float v0, v1, v2;
    if (r >= HALF_S) {
        const float* ab = abar + (row >> 10) * Ddim;
        v0 = x[ob + tid]       + ab[tid];
        v1 = x[ob + tid + 256] + ab[tid + 256];
        v2 = x[ob + tid + 512] + ab[tid + 512];
        x1[ob + tid]       = v0;
        x1[ob + tid + 256] = v1;
        x1[ob + tid + 512] = v2;
    } else {
        v0 = x1[ob + tid];
        v1 = x1[ob + tid + 256];
        v2 = x1[ob + tid + 512];
    }
    ln_row_to_fp16(v0, v1, v2, g, b, x2, ob, tid);
}

// ---------------- fp16 1-pass HMMA GEMM: C = A @ B ----------------
// 128x128 CTA tile, 8 warps (warp tile 64x32), BK=64, 3-stage, 2 CTAs/SM.
// MODE 0: fp32 out (+bias, optional res). MODE 1: fp16 out (+bias, +RELU).
// MODE 2: QKV trio fp16 out; seg 0 (q) computes only lower-512 row tiles.
// HALFM: A/res/out rows are the lower 512 of each batch.
// ABAR: blocks with bn >= N/128 each compute one 32-col abar unit (192 blocks).
#define GLDS  144u
#define GTBA  18432u     // 128 * 144
#define GSTG  36864u     // 2 tiles
#define GSM   110592     // 3 stages

template<int MODE, bool RELU, bool RES, bool HALFM, bool ABAR>
__global__ __launch_bounds__(256, 2) void gemm_mma(
    const __half* __restrict__ A, const __half* __restrict__ B,
    const float* __restrict__ bias0, const float* __restrict__ bias1,
    const float* __restrict__ bias2, const float* __restrict__ res,
    float* __restrict__ outF,
    __half* __restrict__ o0, __half* __restrict__ o1, __half* __restrict__ o2,
    const float* __restrict__ ctxbar, const float* __restrict__ Wo32,
    float* __restrict__ abar,
    int N, int K)
{
    extern __shared__ char smem[];
    uint32_t sbase = smem_u32(smem);
    int tid = threadIdx.x;
    int lane = tid & 31, wid = tid >> 5;
    int wm = wid >> 2, wn = wid & 3;
    int bn = blockIdx.x, bm = blockIdx.y;

    if (ABAR && bn >= N / 128) {
        // ---- one abar unit per block: u in [0,192): b = u/24, n0 = (u%24)*32 ----
        float* red = (float*)smem;   // 8 x 33 floats
        int u = (bn - N / 128) * 32 + bm;
        int b = u / 24;
        int n = (u % 24) * 32 + lane;
        const float* cb = ctxbar + b * Ddim;
        float s = 0.f;
        #pragma unroll 8
        for (int k = wid; k < Ddim; k += 8)
            s += cb[k] * Wo32[(size_t)k * Ddim + n];
        red[wid * 33 + lane] = s;
        __syncthreads();
        if (wid == 0) {
            float t = bias0[n];
            #pragma unroll
            for (int i = 0; i < 8; i++) t += red[i * 33 + lane];
            abar[b * Ddim + n] = t;
        }
        return;
    }

    int seg = 0;
    if (MODE == 2) {
        seg = (bn * 128) / Ddim;
        if (seg == 0 && (bm & 7) >= 4) return;   // q tiles only for lower rows
    }

    int rowg = HALFM ? ((bm >> 2) * Sdim + (bm & 3) * 128) : bm * 128;

    const __half* pA = A + (size_t)rowg * K;
    const __half* pB = B + (size_t)(bn * 128) * K;

    int CH = K >> 6;

    auto load_chunk = [&](int c, int stg){
        int c0 = c * 64;
        uint32_t sb = sbase + (uint32_t)stg * GSTG;
        #pragma unroll
        for (int i = 0; i < 8; i++) {
            int g = i * 256 + tid;
            int tI = g >> 10;
            int w  = g & 1023;
            int rr = w >> 3;
            int cc = w & 7;
            const __half* base = tI ? pB : pA;
            const __half* gp = base + (size_t)rr * K + c0 + cc * 8;
            uint32_t s = sb + (uint32_t)tI * GTBA + (uint32_t)rr * GLDS + (uint32_t)cc * 16;
            CP_ASYNC16(s, gp);
        }
        CP_COMMIT();
    };

    load_chunk(0, 0);
    load_chunk(1, 1);

    float acc[4][4][4];
    #pragma unroll
    for (int i = 0; i < 4; i++)
        #pragma unroll
        for (int j = 0; j < 4; j++)
            #pragma unroll
            for (int e = 0; e < 4; e++) acc[i][j][e] = 0.f;

    uint32_t a_lane = (uint32_t)((lane & 15) * GLDS + (lane >> 4) * 16);
    uint32_t b_lane = (uint32_t)((lane & 7) * GLDS + ((lane >> 3) & 1) * 16 + (lane >> 4) * (8 * GLDS));

    for (int c = 0; c < CH; c++) {
        if (c + 1 < CH) { CP_WAIT1(); } else { CP_WAIT0(); }
        __syncthreads();
        if (c + 2 < CH) load_chunk(c + 2, (c + 2) % 3);

        uint32_t stg = sbase + (uint32_t)(c % 3) * GSTG;
        uint32_t aS = stg, bS = stg + GTBA;

        #pragma unroll
        for (int ks = 0; ks < 4; ks++) {
            uint32_t ko = (uint32_t)ks * 32;
            uint32_t ah[4][4], bh[2][4];
            #pragma unroll
            for (int i = 0; i < 4; i++) {
                uint32_t off = (uint32_t)((wm * 64 + i * 16) * GLDS) + a_lane + ko;
                LDSM4(ah[i], aS + off);
            }
            #pragma unroll
            for (int jp = 0; jp < 2; jp++) {
                uint32_t off = (uint32_t)((wn * 32 + jp * 16) * GLDS) + b_lane + ko;
                LDSM4(bh[jp], bS + off);
            }
            #pragma unroll
            for (int i = 0; i < 4; i++)
                #pragma unroll
                for (int j = 0; j < 4; j++)
                    MMA16816(acc[i][j], ah[i], &bh[j >> 1][(j & 1) * 2]);
        }
    }

    // epilogue
    const float* bsel = bias0;
    __half* Hsel = o0;
    if (MODE == 2) {
        bsel = (seg == 0) ? bias0 : (seg == 1) ? bias1 : bias2;
        Hsel = (seg == 0) ? o0 : (seg == 1) ? o1 : o2;
    }
    int ostride = (MODE == 2) ? Ddim : N;
    int r_base = rowg + wm * 64 + (lane >> 2);
    int c_base = bn * 128 + wn * 32 + (lane & 3) * 2 - ((MODE == 2) ? seg * Ddim : 0);

    #pragma unroll
    for (int i = 0; i < 4; i++) {
        #pragma unroll
        for (int j = 0; j < 4; j++) {
            int row0 = r_base + i * 16;
            int col  = c_base + j * 8;
            float2 bv = *(const float2*)(bsel + col);
            float v00 = acc[i][j][0] + bv.x, v01 = acc[i][j][1] + bv.y;
            float v10 = acc[i][j][2] + bv.x, v11 = acc[i][j][3] + bv.y;
            size_t ox0 = (size_t)row0 * ostride + col;
            size_t ox1 = ox0 + (size_t)8 * ostride;
            if (MODE == 0 && RES) {
                float2 r0 = *(const float2*)(res + ox0);
                float2 r1 = *(const float2*)(res + ox1);
                v00 += r0.x; v01 += r0.y; v10 += r1.x; v11 += r1.y;
            }
            if (RELU) {
                v00 = fmaxf(v00, 0.f); v01 = fmaxf(v01, 0.f);
                v10 = fmaxf(v10, 0.f); v11 = fmaxf(v11, 0.f);
            }
            if (MODE == 0) {
                *(float2*)(outF + ox0) = make_float2(v00, v01);
                *(float2*)(outF + ox1) = make_float2(v10, v11);
            } else {
                *(uint32_t*)(Hsel + ox0) = pack2h(v00, v01);
                *(uint32_t*)(Hsel + ox1) = pack2h(v10, v11);
            }
        }
    }
}

// ---------------- HMMA flash attention + fused ctxmean blocks ----------------
// grid (96, 10): qt < 8 -> attention tile; qt >= 8 -> ctxmean block.
#define AST 144u
#define PST 272u
#define A_SQH 0u
#define A_SK  9216u       // 2 stages x 18432
#define A_SV  46080u      // 2 stages x 18432
#define A_SP  82944u
#define A_PSUM 100352u
#define ATTN_SMEM 100864

__global__ __launch_bounds__(256) void attn_mma_kernel(
    const __half* __restrict__ Qh, const __half* __restrict__ Kh,
    const __half* __restrict__ Vh, __half* __restrict__ OH,
    float* __restrict__ ctxbar)
{
    extern __shared__ char smraw[];
    uint32_t S = smem_u32(smraw);
    int bh = blockIdx.x, qt = blockIdx.y;
    int tid = threadIdx.x, lane = tid & 31, wid = tid >> 5;

    if (qt >= 8) {
        __shared__ float red[8][33];
        int idx = bh * 2 + (qt - 8);
        int b = idx / 24;
        int n0 = (idx % 24) * 32;
        int tx = tid & 31, ty = tid >> 5;
        size_t base = ((size_t)b * Sdim + ty) * Ddim + n0 + tx;
        float s = 0.f;
        #pragma unroll 4
        for (int r = ty; r < Sdim; r += 8)
            s += __half2float(Vh[base + (size_t)(r - ty) * Ddim]);
        red[ty][tx] = s;
        __syncthreads();
        if (ty == 0) {
            float t = 0.f;
            #pragma unroll
            for (int i = 0; i < 8; i++) t += red[i][tx];
            ctxbar[b * Ddim + n0 + tx] = t * (1.0f / Sdim);
        }
        return;
    }

    float* psum = (float*)(smraw + A_PSUM);
    int b = bh / Hn, h = bh % Hn;
    int wm = wid >> 1, wn = wid & 1;

    const size_t cb = (size_t)h * DHn;
    const __half* Qg = Qh + ((size_t)(b * Sdim + qt * 64)) * Ddim + cb;
    const __half* Kg = Kh + ((size_t)(b * Sdim)) * Ddim + cb;
    const __half* Vg = Vh + ((size_t)(b * Sdim)) * Ddim + cb;

    auto load_kv = [&](int t, int s){
        uint32_t kb = S + A_SK + (uint32_t)s * 18432u;
        uint32_t vb = S + A_SV + (uint32_t)s * 18432u;
        #pragma unroll
        for (int i = 0; i < 8; i++) {
            int idx = ((i & 3) << 8) + tid;
            int r = idx >> 3, c = idx & 7;
            const __half* src = (i < 4 ? Kg : Vg) + (size_t)(t * 128 + r) * Ddim + c * 8;
            uint32_t dst = (i < 4 ? kb : vb) + (uint32_t)r * AST + (uint32_t)c * 16;
            CP_ASYNC16(dst, src);
        }
        CP_COMMIT();
    };

    #pragma unroll
    for (int i = 0; i < 2; i++) {
        int idx = (i << 8) + tid;
        int r = idx >> 3, c = idx & 7;
        const __half* src = Qg + (size_t)r * Ddim + c * 8;
        CP_ASYNC16(S + A_SQH + (uint32_t)r * AST + (uint32_t)c * 16, src);
    }
    {
        uint32_t kb = S + A_SK, vb = S + A_SV;
        #pragma unroll
        for (int i = 0; i < 8; i++) {
            int idx = ((i & 3) << 8) + tid;
            int r = idx >> 3, c = idx & 7;
            const __half* src = (i < 4 ? Kg : Vg) + (size_t)r * Ddim + c * 8;
            uint32_t dst = (i < 4 ? kb : vb) + (uint32_t)r * AST + (uint32_t)c * 16;
            CP_ASYNC16(dst, src);
        }
        CP_COMMIT();
    }
    load_kv(1, 1);

    float oacc[4][4];
    #pragma unroll
    for (int j = 0; j < 4; j++)
        #pragma unroll
        for (int e = 0; e < 4; e++) oacc[j][e] = 0.f;
    float l0 = 0.f, l1 = 0.f;

    uint32_t qF[4][4];
    int r0 = wm * 16 + (lane >> 2);

    const int NKT = Sdim / 128;
    for (int t = 0; t < NKT; t++) {
        int s = t & 1;
        if (t + 1 < NKT) { CP_WAIT1(); } else { CP_WAIT0(); }
        __syncthreads();

        if (t == 0) {
            #pragma unroll
            for (int ks = 0; ks < 4; ks++) {
                uint32_t off = (uint32_t)((wm * 16 + (lane & 15)) * AST)
                             + (uint32_t)((lane >> 4) * 16) + (uint32_t)ks * 32;
                LDSM4(qF[ks], S + A_SQH + off);
            }
        }

        uint32_t kb = S + A_SK + (uint32_t)s * 18432u;
        uint32_t vb = S + A_SV + (uint32_t)s * 18432u;

        float sacc[8][4];
        #pragma unroll
        for (int j = 0; j < 8; j++)
            #pragma unroll
            for (int e = 0; e < 4; e++) sacc[j][e] = 0.f;

        uint32_t bl_lane = (uint32_t)((lane & 7) * AST + ((lane >> 3) & 1) * 16
                                      + (lane >> 4) * (8 * AST));
        #pragma unroll
        for (int ks = 0; ks < 4; ks++) {
            uint32_t kf[4][4];
            #pragma unroll
            for (int np = 0; np < 4; np++) {
                uint32_t off = (uint32_t)((wn * 64 + np * 16) * AST) + bl_lane + (uint32_t)ks * 32;
                LDSM4(kf[np], kb + off);
            }
            #pragma unroll
            for (int j = 0; j < 8; j++)
                MMA16816(sacc[j], qF[ks], &kf[j >> 1][(j & 1) * 2]);
        }

        float s0 = 0.f, s1 = 0.f;
        uint32_t prow0 = S + A_SP + (uint32_t)(r0 * PST);
        uint32_t prow1 = S + A_SP + (uint32_t)((r0 + 8) * PST);
        uint32_t coff = (uint32_t)((wn * 64 + (lane & 3) * 2) * 2);
        #pragma unroll
        for (int j = 0; j < 8; j++) {
            float p00 = __expf(sacc[j][0] * 0.125f);
            float p01 = __expf(sacc[j][1] * 0.125f);
            float p10 = __expf(sacc[j][2] * 0.125f);
            float p11 = __expf(sacc[j][3] * 0.125f);
            s0 += p00 + p01; s1 += p10 + p11;
            uint32_t u0 = pack2h(p00, p01), u1 = pack2h(p10, p11);
            asm volatile("st.shared.b32 [%0], %1;" :: "r"(prow0 + coff + j * 16), "r"(u0) : "memory");
            asm volatile("st.shared.b32 [%0], %1;" :: "r"(prow1 + coff + j * 16), "r"(u1) : "memory");
        }
        l0 += s0; l1 += s1;
        __syncthreads();

        #pragma unroll
        for (int ks = 0; ks < 8; ks++) {
            uint32_t pf[4];
            uint32_t aoff = (uint32_t)((wm * 16 + (lane & 15)) * PST)
                          + (uint32_t)((lane >> 4) * 16) + (uint32_t)ks * 32;
            LDSM4(pf, S + A_SP + aoff);
            #pragma unroll
            for (int np = 0; np < 2; np++) {
                uint32_t vf[4];
                uint32_t voff = (uint32_t)((ks * 16 + (lane & 15)) * AST)
                              + (uint32_t)(wn * 64 + np * 32) + (uint32_t)((lane >> 4) * 16);
                LDSM4T(vf, vb + voff);
                MMA16816(oacc[np * 2 + 0], pf, &vf[0]);
                MMA16816(oacc[np * 2 + 1], pf, &vf[2]);
            }
        }

        __syncthreads();
        if (t + 2 < NKT) load_kv(t + 2, s);
    }

    l0 += __shfl_xor_sync(0xffffffffu, l0, 1);
    l0 += __shfl_xor_sync(0xffffffffu, l0, 2);
    l1 += __shfl_xor_sync(0xffffffffu, l1, 1);
    l1 += __shfl_xor_sync(0xffffffffu, l1, 2);
    if ((lane & 3) == 0) {
        psum[r0 * 2 + wn] = l0;
        psum[(r0 + 8) * 2 + wn] = l1;
    }
    __syncthreads();
    float inv0 = 1.0f / (psum[r0 * 2] + psum[r0 * 2 + 1]);
    float inv1 = 1.0f / (psum[(r0 + 8) * 2] + psum[(r0 + 8) * 2 + 1]);

    size_t grow0 = ((size_t)(b * Sdim + qt * 64 + r0)) * Ddim + cb + wn * 32 + (lane & 3) * 2;
    size_t grow1 = grow0 + (size_t)8 * Ddim;
    #pragma unroll
    for (int j = 0; j < 4; j++) {
        *(uint32_t*)(OH + grow0 + j * 8) = pack2h(oacc[j][0] * inv0, oacc[j][1] * inv0);
        *(uint32_t*)(OH + grow1 + j * 8) = pack2h(oacc[j][2] * inv1, oacc[j][3] * inv1);
    }
}

// ---------------- launcher ----------------
extern "C" void kernel_launch(void* const* d_in, const int* in_sizes, int n_in,
                              void* d_out, int out_size)
{
    const float* x    = (const float*)d_in[0];
    const float* Wq   = (const float*)d_in[1];
    const float* bq   = (const float*)d_in[2];
    const float* Wk   = (const float*)d_in[3];
    const float* bk   = (const float*)d_in[4];
    const float* Wv   = (const float*)d_in[5];
    const float* bv   = (const float*)d_in[6];
    const float* Wo   = (const float*)d_in[7];
    const float* bo   = (const float*)d_in[8];
    const float* ln1g = (const float*)d_in[9];
    const float* ln1b = (const float*)d_in[10];
    const float* ln2g = (const float*)d_in[11];
    const float* ln2b = (const float*)d_in[12];
    const float* W1   = (const float*)d_in[13];
    const float* b1   = (const float*)d_in[14];
    const float* W2   = (const float*)d_in[15];
    const float* b2   = (const float*)d_in[16];
    float* out = (float*)d_out;

    float *x1, *ctxbar, *abar;
    __half *xn, *qh, *kh, *vh, *ct, *x2, *h1;
    __half *wqkv, *wo, *w1, *w2;
    cudaGetSymbolAddress((void**)&x1,  g_x1);
    cudaGetSymbolAddress((void**)&ctxbar, g_ctxbar);
    cudaGetSymbolAddress((void**)&abar,   g_abar);
    cudaGetSymbolAddress((void**)&xn,  g_xn);
    cudaGetSymbolAddress((void**)&qh,  g_qh);
    cudaGetSymbolAddress((void**)&kh,  g_kh);
    cudaGetSymbolAddress((void**)&vh,  g_vh);
    cudaGetSymbolAddress((void**)&ct,  g_ct);
    cudaGetSymbolAddress((void**)&x2,  g_x2);
    cudaGetSymbolAddress((void**)&h1,  g_h1);
    cudaGetSymbolAddress((void**)&wqkv, g_wqkv);
    cudaGetSymbolAddress((void**)&wo,  g_wo);
    cudaGetSymbolAddress((void**)&w1,  g_w1);
    cudaGetSymbolAddress((void**)&w2,  g_w2);

    cudaFuncSetAttribute(attn_mma_kernel, cudaFuncAttributeMaxDynamicSharedMemorySize, ATTN_SMEM);
    cudaFuncSetAttribute(gemm_mma<2,false,false,false,false>, cudaFuncAttributeMaxDynamicSharedMemorySize, GSM);
    cudaFuncSetAttribute(gemm_mma<0,false,true ,true ,true >, cudaFuncAttributeMaxDynamicSharedMemorySize, GSM);
    cudaFuncSetAttribute(gemm_mma<1,true ,false,false,false>, cudaFuncAttributeMaxDynamicSharedMemorySize, GSM);
    cudaFuncSetAttribute(gemm_mma<0,false,true ,false,false>, cudaFuncAttributeMaxDynamicSharedMemorySize, GSM);

    WTab tab;
    tab.e[0] = { Wq, wqkv,               Ddim, Ddim, 0    };
    tab.e[1] = { Wk, wqkv + Ddim*Ddim,   Ddim, Ddim, 576  };
    tab.e[2] = { Wv, wqkv + 2*Ddim*Ddim, Ddim, Ddim, 1152 };
    tab.e[3] = { Wo, wo,                 Ddim, Ddim, 1728 };
    tab.e[4] = { W1, w1,                 Ddim, MLPn, 2304 };
    tab.e[5] = { W2, w2,                 MLPn, Ddim, 4608 };

    // 1. weight transpose + LN1
    prep_kernel<<<WTILES + Rn, 256>>>(tab, x, ln1g, ln1b, xn);

    // 2. fused QKV (q: lower rows only; k,v: all rows)
    gemm_mma<2,false,false,false,false><<<dim3(3*Ddim/128, Rn/128), 256, GSM>>>(
        xn, wqkv, bq, bk, bv, nullptr, nullptr,
        qh, kh, vh, nullptr, nullptr, nullptr, 3*Ddim, Ddim);

    // 3. attention (rows < 512) + fused ctxmean blocks
    attn_mma_kernel<<<dim3(Bdim*Hn, 10), 256, ATTN_SMEM>>>(qh, kh, vh, ct, ctxbar);

    // 4. Wo + residual, lower rows; bn in 6..11 -> 192 one-unit abar blocks (hidden)
    gemm_mma<0,false,true,true,true><<<dim3(Ddim/128 + 6, (Rn/2)/128), 256, GSM>>>(
        ct, wo, bo, nullptr, nullptr, x, x1,
        nullptr, nullptr, nullptr, ctxbar, Wo, abar, Ddim, Ddim);

    // 5. x2 = LN2 all rows; upper rows also build x1 = x + abar
    ln2_all_kernel<<<Rn, 256>>>(x, abar, ln2g, ln2b, x1, x2);

    // 6. MLP1 (ReLU, fp16 out)
    gemm_mma<1,true,false,false,false><<<dim3(MLPn/128, Rn/128), 256, GSM>>>(
        x2, w1, b1, nullptr, nullptr, nullptr, nullptr,
        h1, nullptr, nullptr, nullptr, nullptr, nullptr, MLPn, Ddim);

    // 7. MLP2 + residual -> out
    gemm_mma<0,false,true,false,false><<<dim3(Ddim/128, Rn/128), 256, GSM>>>(
        h1, w2, b2, nullptr, nullptr, x1, out,
        nullptr, nullptr, nullptr, nullptr, nullptr, nullptr, Ddim, MLPn);
}

// round 16
// speedup vs baseline: 1.0544x; 1.0076x over previous
#include <cuda_runtime.h>
#include <cuda_fp16.h>
#include <math.h>
#include <stdint.h>

// ---------------- problem dims ----------------
#define Bdim 8
#define Sdim 1024
#define Ddim 768
#define Hn   12
#define DHn  64
#define MLPn 3072
#define Rn   (Bdim*Sdim)          // 8192 rows
#define HALF_S 512

// ---------------- scratch (device globals) ----------------
__device__ float g_x1[Rn*Ddim];
__device__ float g_ctxbar[Bdim*Ddim];
__device__ float g_abar[Bdim*Ddim];
__device__ __half g_xn [Rn*Ddim];
__device__ __half g_qh [Rn*Ddim];
__device__ __half g_kh [Rn*Ddim];
__device__ __half g_vh [Rn*Ddim];
__device__ __half g_ct [Rn*Ddim];
__device__ __half g_x2 [Rn*Ddim];
__device__ __half g_h1 [Rn*MLPn];
// fp16 transposed weights [N, K] K-major; qkv concatenated [2304, 768]
__device__ __half g_wqkv[3*Ddim*Ddim];
__device__ __half g_wo[Ddim*Ddim];
__device__ __half g_w1[MLPn*Ddim];
__device__ __half g_w2[Ddim*MLPn];

// ---------------- helpers ----------------
__device__ __forceinline__ uint32_t smem_u32(const void* p){
    uint32_t a;
    asm("{ .reg .u64 t; cvta.to.shared.u64 t, %1; cvt.u32.u64 %0, t; }" : "=r"(a) : "l"(p));
    return a;
}
__device__ __forceinline__ uint32_t pack2h(float a, float b){
    __half2 h = __floats2half2_rn(a, b);
    return *(uint32_t*)&h;
}

#define CP_ASYNC16(sdst, gsrc) \
    asm volatile("cp.async.cg.shared.global [%0], [%1], 16;" :: "r"(sdst), "l"(gsrc) : "memory")
#define CP_COMMIT()  asm volatile("cp.async.commit_group;" ::: "memory")
#define CP_WAIT1()   asm volatile("cp.async.wait_group 1;" ::: "memory")
#define CP_WAIT0()   asm volatile("cp.async.wait_group 0;" ::: "memory")

#define LDSM4(R, A) \
    asm volatile("ldmatrix.sync.aligned.m8n8.x4.shared.b16 {%0,%1,%2,%3}, [%4];" \
        : "=r"((R)[0]), "=r"((R)[1]), "=r"((R)[2]), "=r"((R)[3]) : "r"(A))
#define LDSM4T(R, A) \
    asm volatile("ldmatrix.sync.aligned.m8n8.x4.trans.shared.b16 {%0,%1,%2,%3}, [%4];" \
        : "=r"((R)[0]), "=r"((R)[1]), "=r"((R)[2]), "=r"((R)[3]) : "r"(A))

#define MMA16816(D, Aa, Bb) \
    asm volatile("mma.sync.aligned.m16n8k16.row.col.f32.f16.f16.f32 " \
        "{%0,%1,%2,%3}, {%4,%5,%6,%7}, {%8,%9}, {%0,%1,%2,%3};" \
        : "+f"((D)[0]), "+f"((D)[1]), "+f"((D)[2]), "+f"((D)[3]) \
        : "r"((Aa)[0]), "r"((Aa)[1]), "r"((Aa)[2]), "r"((Aa)[3]), \
          "r"((Bb)[0]), "r"((Bb)[1]))

// ---------------- LayerNorm core (full 768-col row in one block) ----------------
__device__ __forceinline__ void ln_row_to_fp16(
    float v0, float v1, float v2,
    const float* __restrict__ g, const float* __restrict__ b,
    __half* __restrict__ y, size_t ob, int tid)
{
    float s = v0 + v1 + v2;
    float q = v0*v0 + v1*v1 + v2*v2;
    #pragma unroll
    for (int o = 16; o; o >>= 1) {
        s += __shfl_xor_sync(0xffffffffu, s, o);
        q += __shfl_xor_sync(0xffffffffu, q, o);
    }
    __shared__ float rs[8], rq[8];
    if ((tid & 31) == 0) { rs[tid >> 5] = s; rq[tid >> 5] = q; }
    __syncthreads();
    float ts = 0.f, tq = 0.f;
    #pragma unroll
    for (int i = 0; i < 8; i++) { ts += rs[i]; tq += rq[i]; }
    float mu   = ts * (1.0f / Ddim);
    float var  = tq * (1.0f / Ddim) - mu * mu;
    float rstd = rsqrtf(var + 1e-6f);

    y[ob + tid]       = __float2half((v0 - mu) * rstd * g[tid]       + b[tid]);
    y[ob + tid + 256] = __float2half((v1 - mu) * rstd * g[tid + 256] + b[tid + 256]);
    y[ob + tid + 512] = __float2half((v2 - mu) * rstd * g[tid + 512] + b[tid + 512]);
}

// ---------------- prep: weight transpose (blocks 0..6911) + LN1 (rest) ----------------
struct WEnt { const float* src; __half* dh; int K, N, tile0; };
struct WTab { WEnt e[6]; };
#define WTILES 6912

__global__ __launch_bounds__(256) void prep_kernel(
    WTab tab, const float* __restrict__ x,
    const float* __restrict__ ln1g, const float* __restrict__ ln1b,
    __half* __restrict__ xn)
{
    int bt = blockIdx.x;
    int tid = threadIdx.x;
    if (bt < WTILES) {
        __shared__ float t[32][33];
        int ei = 0;
        #pragma unroll
        for (int i = 1; i < 6; i++) if (bt >= tab.e[i].tile0) ei = i;
        const WEnt w = tab.e[ei];
        int lt = bt - w.tile0;
        int nt = w.N / 32;
        int n0 = (lt % nt) * 32, k0 = (lt / nt) * 32;
        int tx = tid & 31, ty = tid >> 5;
        #pragma unroll
        for (int i = ty; i < 32; i += 8)
            t[i][tx] = w.src[(size_t)(k0 + i) * w.N + n0 + tx];
        __syncthreads();
        #pragma unroll
        for (int i = ty; i < 32; i += 8)
            w.dh[(size_t)(n0 + i) * w.K + k0 + tx] = __float2half(t[tx][i]);
    } else {
        int row = bt - WTILES;
        size_t ob = (size_t)row * Ddim;
        float v0 = x[ob + tid], v1 = x[ob + tid + 256], v2 = x[ob + tid + 512];
        ln_row_to_fp16(v0, v1, v2, ln1g, ln1b, xn, ob, tid);
    }
}

// ---------------- ln2_all: x2 = LN2(x1) all rows; upper rows build x1 = x + abar ----------------
__global__ __launch_bounds__(256) void ln2_all_kernel(
    const float* __restrict__ x, const float* __restrict__ abar,
    const float* __restrict__ g, const float* __restrict__ b,
    float* __restrict__ x1, __half* __restrict__ x2)
{
    int row = blockIdx.x;
    int r = row & (Sdim - 1);
    size_t ob = (size_t)row * Ddim;
    int tid = threadIdx.x;
    float v0, v1, v2;
    if (r >= HALF_S) {
        const float* ab = abar + (row >> 10) * Ddim;
        v0 = x[ob + tid]       + ab[tid];
        v1 = x[ob + tid + 256] + ab[tid + 256];
        v2 = x[ob + tid + 512] + ab[tid + 512];
        x1[ob + tid]       = v0;
        x1[ob + tid + 256] = v1;
        x1[ob + tid + 512] = v2;
    } else {
        v0 = x1[ob + tid];
        v1 = x1[ob + tid + 256];
        v2 = x1[ob + tid + 512];
    }
    ln_row_to_fp16(v0, v1, v2, g, b, x2, ob, tid);
}

// ---------------- fp16 1-pass HMMA GEMM: C = A @ B ----------------
// 128x128 CTA tile, 8 warps (warp tile 64x32), BK=64, 3-stage, 2 CTAs/SM.
// MODE 0: fp32 out (+bias, optional res). MODE 1: fp16 out (+bias, +RELU).
// MODE 2: QKV trio fp16 out; seg 0 (q) computes only lower-512 row tiles.
// HALFM: A/res/out rows are the lower 512 of each batch.
// ABAR: blocks with bn >= N/128 each compute one 32-col abar unit (192 blocks)
//       using B's fp16 rows (contiguous) dotted with ctxbar.
#define GLDS  144u
#define GTBA  18432u     // 128 * 144
#define GSTG  36864u     // 2 tiles
#define GSM   110592     // 3 stages

template<int MODE, bool RELU, bool RES, bool HALFM, bool ABAR>
__global__ __launch_bounds__(256, 2) void gemm_mma(
    const __half* __restrict__ A, const __half* __restrict__ B,
    const float* __restrict__ bias0, const float* __restrict__ bias1,
    const float* __restrict__ bias2, const float* __restrict__ res,
    float* __restrict__ outF,
    __half* __restrict__ o0, __half* __restrict__ o1, __half* __restrict__ o2,
    const float* __restrict__ ctxbar, float* __restrict__ abar,
    int N, int K)
{
    extern __shared__ char smem[];
    uint32_t sbase = smem_u32(smem);
    int tid = threadIdx.x;
    int lane = tid & 31, wid = tid >> 5;
    int wm = wid >> 2, wn = wid & 3;
    int bn = blockIdx.x, bm = blockIdx.y;

    if (ABAR && bn >= N / 128) {
        // ---- one abar unit per block: u in [0,192): b = u/24, n0 = (u%24)*32 ----
        // warp w handles n = n0 + g*8 + w; contiguous fp16 B rows dotted with cb.
        int u = (bn - N / 128) * 32 + bm;
        int b = u / 24;
        int n0 = (u % 24) * 32;
        const float* cb = ctxbar + b * Ddim;
        #pragma unroll
        for (int g = 0; g < 4; g++) {
            int n = n0 + g * 8 + wid;
            const __half* wrow = B + (size_t)n * (size_t)K;
            float s = 0.f;
            #pragma unroll
            for (int it = 0; it < 3; it++) {
                int k = it * 256 + lane * 8;
                uint4 pk = *(const uint4*)(wrow + k);
                const __half2* ph = (const __half2*)&pk;
                #pragma unroll
                for (int e = 0; e < 4; e++) {
                    float2 wv = __half22float2(ph[e]);
                    s += wv.x * cb[k + e*2] + wv.y * cb[k + e*2 + 1];
                }
            }
            #pragma unroll
            for (int o = 16; o; o >>= 1)
                s += __shfl_xor_sync(0xffffffffu, s, o);
            if (lane == 0) abar[b * Ddim + n] = s + bias0[n];
        }
        return;
    }

    int seg = 0;
    if (MODE == 2) {
        seg = (bn * 128) / Ddim;
        if (seg == 0 && (bm & 7) >= 4) return;   // q tiles only for lower rows
    }

    int rowg = HALFM ? ((bm >> 2) * Sdim + (bm & 3) * 128) : bm * 128;

    const __half* pA = A + (size_t)rowg * K;
    const __half* pB = B + (size_t)(bn * 128) * K;

    int CH = K >> 6;

    auto load_chunk = [&](int c, int stg){
        int c0 = c * 64;
        uint32_t sb = sbase + (uint32_t)stg * GSTG;
        #pragma unroll
        for (int i = 0; i < 8; i++) {
            int g = i * 256 + tid;
            int tI = g >> 10;
            int w  = g & 1023;
            int rr = w >> 3;
            int cc = w & 7;
            const __half* base = tI ? pB : pA;
            const __half* gp = base + (size_t)rr * K + c0 + cc * 8;
            uint32_t s = sb + (uint32_t)tI * GTBA + (uint32_t)rr * GLDS + (uint32_t)cc * 16;
            CP_ASYNC16(s, gp);
        }
        CP_COMMIT();
    };

    load_chunk(0, 0);
    load_chunk(1, 1);

    float acc[4][4][4];
    #pragma unroll
    for (int i = 0; i < 4; i++)
        #pragma unroll
        for (int j = 0; j < 4; j++)
            #pragma unroll
            for (int e = 0; e < 4; e++) acc[i][j][e] = 0.f;

    uint32_t a_lane = (uint32_t)((lane & 15) * GLDS + (lane >> 4) * 16);
    uint32_t b_lane = (uint32_t)((lane & 7) * GLDS + ((lane >> 3) & 1) * 16 + (lane >> 4) * (8 * GLDS));

    for (int c = 0; c < CH; c++) {
        if (c + 1 < CH) { CP_WAIT1(); } else { CP_WAIT0(); }
        __syncthreads();
        if (c + 2 < CH) load_chunk(c + 2, (c + 2) % 3);

        uint32_t stg = sbase + (uint32_t)(c % 3) * GSTG;
        uint32_t aS = stg, bS = stg + GTBA;

        #pragma unroll
        for (int ks = 0; ks < 4; ks++) {
            uint32_t ko = (uint32_t)ks * 32;
            uint32_t ah[4][4], bh[2][4];
            #pragma unroll
            for (int i = 0; i < 4; i++) {
                uint32_t off = (uint32_t)((wm * 64 + i * 16) * GLDS) + a_lane + ko;
                LDSM4(ah[i], aS + off);
            }
            #pragma unroll
            for (int jp = 0; jp < 2; jp++) {
                uint32_t off = (uint32_t)((wn * 32 + jp * 16) * GLDS) + b_lane + ko;
                LDSM4(bh[jp], bS + off);
            }
            #pragma unroll
            for (int i = 0; i < 4; i++)
                #pragma unroll
                for (int j = 0; j < 4; j++)
                    MMA16816(acc[i][j], ah[i], &bh[j >> 1][(j & 1) * 2]);
        }
    }

    // epilogue
    const float* bsel = bias0;
    __half* Hsel = o0;
    if (MODE == 2) {
        bsel = (seg == 0) ? bias0 : (seg == 1) ? bias1 : bias2;
        Hsel = (seg == 0) ? o0 : (seg == 1) ? o1 : o2;
    }
    int ostride = (MODE == 2) ? Ddim : N;
    int r_base = rowg + wm * 64 + (lane >> 2);
    int c_base = bn * 128 + wn * 32 + (lane & 3) * 2 - ((MODE == 2) ? seg * Ddim : 0);

    #pragma unroll
    for (int i = 0; i < 4; i++) {
        #pragma unroll
        for (int j = 0; j < 4; j++) {
            int row0 = r_base + i * 16;
            int col  = c_base + j * 8;
            float2 bv = *(const float2*)(bsel + col);
            float v00 = acc[i][j][0] + bv.x, v01 = acc[i][j][1] + bv.y;
            float v10 = acc[i][j][2] + bv.x, v11 = acc[i][j][3] + bv.y;
            size_t ox0 = (size_t)row0 * ostride + col;
            size_t ox1 = ox0 + (size_t)8 * ostride;
            if (MODE == 0 && RES) {
                float2 r0 = *(const float2*)(res + ox0);
                float2 r1 = *(const float2*)(res + ox1);
                v00 += r0.x; v01 += r0.y; v10 += r1.x; v11 += r1.y;
            }
            if (RELU) {
                v00 = fmaxf(v00, 0.f); v01 = fmaxf(v01, 0.f);
                v10 = fmaxf(v10, 0.f); v11 = fmaxf(v11, 0.f);
            }
            if (MODE == 0) {
                *(float2*)(outF + ox0) = make_float2(v00, v01);
                *(float2*)(outF + ox1) = make_float2(v10, v11);
            } else {
                *(uint32_t*)(Hsel + ox0) = pack2h(v00, v01);
                *(uint32_t*)(Hsel + ox1) = pack2h(v10, v11);
            }
        }
    }
}

// ---------------- HMMA flash attention + fused ctxmean blocks ----------------
// grid (96, 10): qt < 8 -> attention tile; qt >= 8 -> ctxmean block.
#define AST 144u
#define PST 272u
#define A_SQH 0u
#define A_SK  9216u       // 2 stages x 18432
#define A_SV  46080u      // 2 stages x 18432
#define A_SP  82944u
#define A_PSUM 100352u
#define ATTN_SMEM 100864

__global__ __launch_bounds__(256) void attn_mma_kernel(
    const __half* __restrict__ Qh, const __half* __restrict__ Kh,
    const __half* __restrict__ Vh, __half* __restrict__ OH,
    float* __restrict__ ctxbar)
{
    extern __shared__ char smraw[];
    uint32_t S = smem_u32(smraw);
    int bh = blockIdx.x, qt = blockIdx.y;
    int tid = threadIdx.x, lane = tid & 31, wid = tid >> 5;

    if (qt >= 8) {
        __shared__ float red[8][33];
        int idx = bh * 2 + (qt - 8);
        int b = idx / 24;
        int n0 = (idx % 24) * 32;
        int tx = tid & 31, ty = tid >> 5;
        size_t base = ((size_t)b * Sdim + ty) * Ddim + n0 + tx;
        float s = 0.f;
        #pragma unroll 4
        for (int r = ty; r < Sdim; r += 8)
            s += __half2float(Vh[base + (size_t)(r - ty) * Ddim]);
        red[ty][tx] = s;
        __syncthreads();
        if (ty == 0) {
            float t = 0.f;
            #pragma unroll
            for (int i = 0; i < 8; i++) t += red[i][tx];
            ctxbar[b * Ddim + n0 + tx] = t * (1.0f / Sdim);
        }
        return;
    }

    float* psum = (float*)(smraw + A_PSUM);
    int b = bh / Hn, h = bh % Hn;
    int wm = wid >> 1, wn = wid & 1;

    const size_t cb = (size_t)h * DHn;
    const __half* Qg = Qh + ((size_t)(b * Sdim + qt * 64)) * Ddim + cb;
    const __half* Kg = Kh + ((size_t)(b * Sdim)) * Ddim + cb;
    const __half* Vg = Vh + ((size_t)(b * Sdim)) * Ddim + cb;

    auto load_kv = [&](int t, int s){
        uint32_t kb = S + A_SK + (uint32_t)s * 18432u;
        uint32_t vb = S + A_SV + (uint32_t)s * 18432u;
        #pragma unroll
        for (int i = 0; i < 8; i++) {
            int idx = ((i & 3) << 8) + tid;
            int r = idx >> 3, c = idx & 7;
            const __half* src = (i < 4 ? Kg : Vg) + (size_t)(t * 128 + r) * Ddim + c * 8;
            uint32_t dst = (i < 4 ? kb : vb) + (uint32_t)r * AST + (uint32_t)c * 16;
            CP_ASYNC16(dst, src);
        }
        CP_COMMIT();
    };

    #pragma unroll
    for (int i = 0; i < 2; i++) {
        int idx = (i << 8) + tid;
        int r = idx >> 3, c = idx & 7;
        const __half* src = Qg + (size_t)r * Ddim + c * 8;
        CP_ASYNC16(S + A_SQH + (uint32_t)r * AST + (uint32_t)c * 16, src);
    }
    {
        uint32_t kb = S + A_SK, vb = S + A_SV;
        #pragma unroll
        for (int i = 0; i < 8; i++) {
            int idx = ((i & 3) << 8) + tid;
            int r = idx >> 3, c = idx & 7;
            const __half* src = (i < 4 ? Kg : Vg) + (size_t)r * Ddim + c * 8;
            uint32_t dst = (i < 4 ? kb : vb) + (uint32_t)r * AST + (uint32_t)c * 16;
            CP_ASYNC16(dst, src);
        }
        CP_COMMIT();
    }
    load_kv(1, 1);

    float oacc[4][4];
    #pragma unroll
    for (int j = 0; j < 4; j++)
        #pragma unroll
        for (int e = 0; e < 4; e++) oacc[j][e] = 0.f;
    float l0 = 0.f, l1 = 0.f;

    uint32_t qF[4][4];
    int r0 = wm * 16 + (lane >> 2);

    const int NKT = Sdim / 128;
    for (int t = 0; t < NKT; t++) {
        int s = t & 1;
        if (t + 1 < NKT) { CP_WAIT1(); } else { CP_WAIT0(); }
        __syncthreads();

        if (t == 0) {
            #pragma unroll
            for (int ks = 0; ks < 4; ks++) {
                uint32_t off = (uint32_t)((wm * 16 + (lane & 15)) * AST)
                             + (uint32_t)((lane >> 4) * 16) + (uint32_t)ks * 32;
                LDSM4(qF[ks], S + A_SQH + off);
            }
        }

        uint32_t kb = S + A_SK + (uint32_t)s * 18432u;
        uint32_t vb = S + A_SV + (uint32_t)s * 18432u;

        float sacc[8][4];
        #pragma unroll
        for (int j = 0; j < 8; j++)
            #pragma unroll
            for (int e = 0; e < 4; e++) sacc[j][e] = 0.f;

        uint32_t bl_lane = (uint32_t)((lane & 7) * AST + ((lane >> 3) & 1) * 16
                                      + (lane >> 4) * (8 * AST));
        #pragma unroll
        for (int ks = 0; ks < 4; ks++) {
            uint32_t kf[4][4];
            #pragma unroll
            for (int np = 0; np < 4; np++) {
                uint32_t off = (uint32_t)((wn * 64 + np * 16) * AST) + bl_lane + (uint32_t)ks * 32;
                LDSM4(kf[np], kb + off);
            }
            #pragma unroll
            for (int j = 0; j < 8; j++)
                MMA16816(sacc[j], qF[ks], &kf[j >> 1][(j & 1) * 2]);
        }

        float s0 = 0.f, s1 = 0.f;
        uint32_t prow0 = S + A_SP + (uint32_t)(r0 * PST);
        uint32_t prow1 = S + A_SP + (uint32_t)((r0 + 8) * PST);
        uint32_t coff = (uint32_t)((wn * 64 + (lane & 3) * 2) * 2);
        #pragma unroll
        for (int j = 0; j < 8; j++) {
            float p00 = __expf(sacc[j][0] * 0.125f);
            float p01 = __expf(sacc[j][1] * 0.125f);
            float p10 = __expf(sacc[j][2] * 0.125f);
            float p11 = __expf(sacc[j][3] * 0.125f);
            s0 += p00 + p01; s1 += p10 + p11;
            uint32_t u0 = pack2h(p00, p01), u1 = pack2h(p10, p11);
            asm volatile("st.shared.b32 [%0], %1;" :: "r"(prow0 + coff + j * 16), "r"(u0) : "memory");
            asm volatile("st.shared.b32 [%0], %1;" :: "r"(prow1 + coff + j * 16), "r"(u1) : "memory");
        }
        l0 += s0; l1 += s1;
        __syncthreads();

        #pragma unroll
        for (int ks = 0; ks < 8; ks++) {
            uint32_t pf[4];
            uint32_t aoff = (uint32_t)((wm * 16 + (lane & 15)) * PST)
                          + (uint32_t)((lane >> 4) * 16) + (uint32_t)ks * 32;
            LDSM4(pf, S + A_SP + aoff);
            #pragma unroll
            for (int np = 0; np < 2; np++) {
                uint32_t vf[4];
                uint32_t voff = (uint32_t)((ks * 16 + (lane & 15)) * AST)
                              + (uint32_t)(wn * 64 + np * 32) + (uint32_t)((lane >> 4) * 16);
                LDSM4T(vf, vb + voff);
                MMA16816(oacc[np * 2 + 0], pf, &vf[0]);
                MMA16816(oacc[np * 2 + 1], pf, &vf[2]);
            }
        }

        __syncthreads();
        if (t + 2 < NKT) load_kv(t + 2, s);
    }

    l0 += __shfl_xor_sync(0xffffffffu, l0, 1);
    l0 += __shfl_xor_sync(0xffffffffu, l0, 2);
    l1 += __shfl_xor_sync(0xffffffffu, l1, 1);
    l1 += __shfl_xor_sync(0xffffffffu, l1, 2);
    if ((lane & 3) == 0) {
        psum[r0 * 2 + wn] = l0;
        psum[(r0 + 8) * 2 + wn] = l1;
    }
    __syncthreads();
    float inv0 = 1.0f / (psum[r0 * 2] + psum[r0 * 2 + 1]);
    float inv1 = 1.0f / (psum[(r0 + 8) * 2] + psum[(r0 + 8) * 2 + 1]);

    size_t grow0 = ((size_t)(b * Sdim + qt * 64 + r0)) * Ddim + cb + wn * 32 + (lane & 3) * 2;
    size_t grow1 = grow0 + (size_t)8 * Ddim;
    #pragma unroll
    for (int j = 0; j < 4; j++) {
        *(uint32_t*)(OH + grow0 + j * 8) = pack2h(oacc[j][0] * inv0, oacc[j][1] * inv0);
        *(uint32_t*)(OH + grow1 + j * 8) = pack2h(oacc[j][2] * inv1, oacc[j][3] * inv1);
    }
}

// ---------------- launcher ----------------
extern "C" void kernel_launch(void* const* d_in, const int* in_sizes, int n_in,
                              void* d_out, int out_size)
{
    const float* x    = (const float*)d_in[0];
    const float* Wq   = (const float*)d_in[1];
    const float* bq   = (const float*)d_in[2];
    const float* Wk   = (const float*)d_in[3];
    const float* bk   = (const float*)d_in[4];
    const float* Wv   = (const float*)d_in[5];
    const float* bv   = (const float*)d_in[6];
    const float* Wo   = (const float*)d_in[7];
    const float* bo   = (const float*)d_in[8];
    const float* ln1g = (const float*)d_in[9];
    const float* ln1b = (const float*)d_in[10];
    const float* ln2g = (const float*)d_in[11];
    const float* ln2b = (const float*)d_in[12];
    const float* W1   = (const float*)d_in[13];
    const float* b1   = (const float*)d_in[14];
    const float* W2   = (const float*)d_in[15];
    const float* b2   = (const float*)d_in[16];
    float* out = (float*)d_out;

    float *x1, *ctxbar, *abar;
    __half *xn, *qh, *kh, *vh, *ct, *x2, *h1;
    __half *wqkv, *wo, *w1, *w2;
    cudaGetSymbolAddress((void**)&x1,  g_x1);
    cudaGetSymbolAddress((void**)&ctxbar, g_ctxbar);
    cudaGetSymbolAddress((void**)&abar,   g_abar);
    cudaGetSymbolAddress((void**)&xn,  g_xn);
    cudaGetSymbolAddress((void**)&qh,  g_qh);
    cudaGetSymbolAddress((void**)&kh,  g_kh);
    cudaGetSymbolAddress((void**)&vh,  g_vh);
    cudaGetSymbolAddress((void**)&ct,  g_ct);
    cudaGetSymbolAddress((void**)&x2,  g_x2);
    cudaGetSymbolAddress((void**)&h1,  g_h1);
    cudaGetSymbolAddress((void**)&wqkv, g_wqkv);
    cudaGetSymbolAddress((void**)&wo,  g_wo);
    cudaGetSymbolAddress((void**)&w1,  g_w1);
    cudaGetSymbolAddress((void**)&w2,  g_w2);

    cudaFuncSetAttribute(attn_mma_kernel, cudaFuncAttributeMaxDynamicSharedMemorySize, ATTN_SMEM);
    cudaFuncSetAttribute(gemm_mma<2,false,false,false,false>, cudaFuncAttributeMaxDynamicSharedMemorySize, GSM);
    cudaFuncSetAttribute(gemm_mma<0,false,true ,true ,true >, cudaFuncAttributeMaxDynamicSharedMemorySize, GSM);
    cudaFuncSetAttribute(gemm_mma<1,true ,false,false,false>, cudaFuncAttributeMaxDynamicSharedMemorySize, GSM);
    cudaFuncSetAttribute(gemm_mma<0,false,true ,false,false>, cudaFuncAttributeMaxDynamicSharedMemorySize, GSM);

    WTab tab;
    tab.e[0] = { Wq, wqkv,               Ddim, Ddim, 0    };
    tab.e[1] = { Wk, wqkv + Ddim*Ddim,   Ddim, Ddim, 576  };
    tab.e[2] = { Wv, wqkv + 2*Ddim*Ddim, Ddim, Ddim, 1152 };
    tab.e[3] = { Wo, wo,                 Ddim, Ddim, 1728 };
    tab.e[4] = { W1, w1,                 Ddim, MLPn, 2304 };
    tab.e[5] = { W2, w2,                 MLPn, Ddim, 4608 };

    // 1. weight transpose + LN1
    prep_kernel<<<WTILES + Rn, 256>>>(tab, x, ln1g, ln1b, xn);

    // 2. fused QKV (q: lower rows only; k,v: all rows)
    gemm_mma<2,false,false,false,false><<<dim3(3*Ddim/128, Rn/128), 256, GSM>>>(
        xn, wqkv, bq, bk, bv, nullptr, nullptr,
        qh, kh, vh, nullptr, nullptr, 3*Ddim, Ddim);

    // 3. attention (rows < 512) + fused ctxmean blocks
    attn_mma_kernel<<<dim3(Bdim*Hn, 10), 256, ATTN_SMEM>>>(qh, kh, vh, ct, ctxbar);

    // 4. Wo + residual, lower rows; bn in 6..11 -> 192 fp16-dot abar blocks (hidden)
    gemm_mma<0,false,true,true,true><<<dim3(Ddim/128 + 6, (Rn/2)/128), 256, GSM>>>(
        ct, wo, bo, nullptr, nullptr, x, x1,
        nullptr, nullptr, nullptr, ctxbar, abar, Ddim, Ddim);

    // 5. x2 = LN2 all rows; upper rows also build x1 = x + abar
    ln2_all_kernel<<<Rn, 256>>>(x, abar, ln2g, ln2b, x1, x2);

    // 6. MLP1 (ReLU, fp16 out)
    gemm_mma<1,true,false,false,false><<<dim3(MLPn/128, Rn/128), 256, GSM>>>(
        x2, w1, b1, nullptr, nullptr, nullptr, nullptr,
        h1, nullptr, nullptr, nullptr, nullptr, MLPn, Ddim);

    // 7. MLP2 + residual -> out
    gemm_mma<0,false,true,false,false><<<dim3(Ddim/128, Rn/128), 256, GSM>>>(
        h1, w2, b2, nullptr, nullptr, x1, out,
        nullptr, nullptr, nullptr, nullptr, nullptr, Ddim, MLPn);
}